// round 7
// baseline (speedup 1.0000x reference)
#include <cuda_runtime.h>
#include <cuda_bf16.h>
#include <math.h>
#include <cstdint>

#define BATCH 4
#define SEQ   4096
#define EMB   1024
#define HDIM  128

// ---------------------------------------------------------------------------
// scratch (allocation-free: __device__ globals) — all bf16 hi/lo split pairs
// ---------------------------------------------------------------------------
__device__ __nv_bfloat16 g_Qhi[(size_t)BATCH * SEQ * HDIM];
__device__ __nv_bfloat16 g_Qlo[(size_t)BATCH * SEQ * HDIM];
__device__ __nv_bfloat16 g_Khi[(size_t)BATCH * SEQ * HDIM];
__device__ __nv_bfloat16 g_Klo[(size_t)BATCH * SEQ * HDIM];
__device__ __nv_bfloat16 g_Vhi[(size_t)BATCH * SEQ * HDIM];
__device__ __nv_bfloat16 g_Vlo[(size_t)BATCH * SEQ * HDIM];
// split weights: [which][HDIM][EMB], which: 0=K,1=Q,2=V
__device__ __nv_bfloat16 g_Whi[3 * HDIM * EMB];
__device__ __nv_bfloat16 g_Wlo[3 * HDIM * EMB];

// ===========================================================================
// mma.sync / ldmatrix / cp.async helpers (baseline PTX, no 'a' features)
// ===========================================================================
__device__ __forceinline__ uint32_t smem_to_u32(const void* p) {
    uint32_t a;
    asm("{ .reg .u64 t; cvta.to.shared.u64 t, %1; cvt.u32.u64 %0, t; }"
        : "=r"(a) : "l"(p));
    return a;
}

__device__ __forceinline__ void ldsm_x4(uint32_t addr,
    uint32_t& r0, uint32_t& r1, uint32_t& r2, uint32_t& r3) {
    asm volatile("ldmatrix.sync.aligned.m8n8.x4.shared.b16 {%0,%1,%2,%3}, [%4];"
        : "=r"(r0), "=r"(r1), "=r"(r2), "=r"(r3) : "r"(addr));
}

__device__ __forceinline__ void ldsm_x4_t(uint32_t addr,
    uint32_t& r0, uint32_t& r1, uint32_t& r2, uint32_t& r3) {
    asm volatile("ldmatrix.sync.aligned.m8n8.x4.trans.shared.b16 {%0,%1,%2,%3}, [%4];"
        : "=r"(r0), "=r"(r1), "=r"(r2), "=r"(r3) : "r"(addr));
}

__device__ __forceinline__ void mma_bf16(float& c0, float& c1, float& c2, float& c3,
    uint32_t a0, uint32_t a1, uint32_t a2, uint32_t a3, uint32_t b0, uint32_t b1) {
    asm volatile(
        "mma.sync.aligned.m16n8k16.row.col.f32.bf16.bf16.f32 "
        "{%0,%1,%2,%3}, {%4,%5,%6,%7}, {%8,%9}, {%0,%1,%2,%3};"
        : "+f"(c0), "+f"(c1), "+f"(c2), "+f"(c3)
        : "r"(a0), "r"(a1), "r"(a2), "r"(a3), "r"(b0), "r"(b1));
}

#define CP_ASYNC16(dst, src) \
    asm volatile("cp.async.cg.shared.global [%0], [%1], 16;" :: "r"(dst), "l"(src))
#define CP_COMMIT()  asm volatile("cp.async.commit_group;" ::: "memory")
#define CP_WAIT0()   asm volatile("cp.async.wait_group 0;" ::: "memory")

// pack two floats into bf16x2 hi + residual lo
__device__ __forceinline__ void split2(float x0, float x1, uint32_t& hi, uint32_t& lo) {
    __nv_bfloat16 h0 = __float2bfloat16(x0);
    __nv_bfloat16 h1 = __float2bfloat16(x1);
    __nv_bfloat16 g0 = __float2bfloat16(x0 - __bfloat162float(h0));
    __nv_bfloat16 g1 = __float2bfloat16(x1 - __bfloat162float(h1));
    hi = (uint32_t)__bfloat16_as_ushort(h0) | ((uint32_t)__bfloat16_as_ushort(h1) << 16);
    lo = (uint32_t)__bfloat16_as_ushort(g0) | ((uint32_t)__bfloat16_as_ushort(g1) << 16);
}

// ===========================================================================
// Weight split prepass: W (fp32) -> (hi, lo) bf16
// ===========================================================================
__global__ __launch_bounds__(256) void wsplit_kernel(
    const float* __restrict__ Wk,
    const float* __restrict__ Wq,
    const float* __restrict__ Wv)
{
    int idx = blockIdx.x * 256 + threadIdx.x;
    if (idx >= 3 * HDIM * EMB) return;
    int which = idx >> 17;
    int within = idx & ((HDIM * EMB) - 1);
    const float* W = (which == 0) ? Wk : (which == 1) ? Wq : Wv;
    float w = W[within];
    __nv_bfloat16 hi = __float2bfloat16(w);
    __nv_bfloat16 lo = __float2bfloat16(w - __bfloat162float(hi));
    g_Whi[idx] = hi;
    g_Wlo[idx] = lo;
}

// ===========================================================================
// Projection GEMM via mma.sync bf16-split.
// B (weights) double-buffered via cp.async; A single-buffered with register
// prefetch. Footprint 110592 B -> 2 CTAs/SM (the R4/R5 occupancy fix).
// grid (128 m-tiles, 3 heads), 256 threads (8 warps x 16 rows = 128 rows).
// ===========================================================================
#define PR_ROWB  144                 // 64 bf16 = 128B + 16B pad
#define PR_ATILE 18432               // 128*144
#define PR_A     0                   // [hi | lo]  (36864)
#define PR_B0    36864               // [hi | lo]  (36864)
#define PR_B1    73728               // [hi | lo]  (36864)
#define PR_SMEM  110592

extern __shared__ char dsmem[];

__global__ __launch_bounds__(256) void proj_mma_kernel(const float* __restrict__ x)
{
    char* smem = dsmem;
    uint32_t sb = smem_to_u32(smem);
    const int tid  = threadIdx.x;
    const int lane = tid & 31;
    const int w    = tid >> 5;
    const int m0   = blockIdx.x * 128;
    const int which = blockIdx.y;

    // ldmatrix lane offsets
    const uint32_t a_off = (uint32_t)(w * 16 + (lane & 15)) * PR_ROWB
                         + (uint32_t)((lane >> 4) << 3) * 2;
    const uint32_t b_off = (uint32_t)((lane & 7) + ((lane >> 4) << 3)) * PR_ROWB
                         + (uint32_t)(((lane >> 3) & 1) << 3) * 2;

    float o[16][4];
#pragma unroll
    for (int t = 0; t < 16; t++)
#pragma unroll
        for (int k = 0; k < 4; k++) o[t][k] = 0.0f;

    const int a_row  = tid >> 1;
    const int a_half = tid & 1;
    const uint32_t a_dst = (uint32_t)a_row * PR_ROWB + (uint32_t)(a_half * 32) * 2;

    float4 xv[8];
    // ---- prologue: A regs for c=0; B tile c=0 -> buf0 via cp.async ----
    {
        const float* xr = x + (size_t)(m0 + a_row) * EMB + a_half * 32;
#pragma unroll
        for (int i = 0; i < 8; i++) xv[i] = *(const float4*)(xr + i * 4);
#pragma unroll
        for (int j = 0; j < 4; j++) {
            int idx = tid + j * 256;
            int row = idx >> 3, c8 = idx & 7;
            size_t gsrc = (size_t)(which * HDIM + row) * EMB + c8 * 8;
            uint32_t doff = (uint32_t)row * PR_ROWB + (uint32_t)c8 * 16;
            CP_ASYNC16(sb + PR_B0 + doff, (const void*)(g_Whi + gsrc));
            CP_ASYNC16(sb + PR_B0 + PR_ATILE + doff, (const void*)(g_Wlo + gsrc));
        }
        CP_COMMIT();
    }

    for (int c = 0; c < 16; c++) {
        const uint32_t bbuf = (c & 1) ? PR_B1 : PR_B0;

        // ---- 1. convert A regs -> smem (A free: trailing barrier of prev iter) ----
#pragma unroll
        for (int i = 0; i < 8; i++) {
            uint32_t h01, l01, h23, l23;
            split2(xv[i].x, xv[i].y, h01, l01);
            split2(xv[i].z, xv[i].w, h23, l23);
            uint32_t off = a_dst + (uint32_t)(i * 4) * 2;
            *(uint32_t*)(smem + PR_A + off)                = h01;
            *(uint32_t*)(smem + PR_A + off + 4)            = h23;
            *(uint32_t*)(smem + PR_A + PR_ATILE + off)     = l01;
            *(uint32_t*)(smem + PR_A + PR_ATILE + off + 4) = l23;
        }

        // ---- 2. wait for B[c]; make A visible ----
        CP_WAIT0();
        __syncthreads();

        // ---- 3. prefetch next iteration (B -> other buf, x -> regs) ----
        if (c < 15) {
            const int e1 = (c + 1) * 64;
            const float* xr = x + (size_t)(m0 + a_row) * EMB + e1 + a_half * 32;
#pragma unroll
            for (int i = 0; i < 8; i++) xv[i] = *(const float4*)(xr + i * 4);
            const uint32_t bnext = (c & 1) ? PR_B0 : PR_B1;
#pragma unroll
            for (int j = 0; j < 4; j++) {
                int idx = tid + j * 256;
                int row = idx >> 3, c8 = idx & 7;
                size_t gsrc = (size_t)(which * HDIM + row) * EMB + e1 + c8 * 8;
                uint32_t doff = (uint32_t)row * PR_ROWB + (uint32_t)c8 * 16;
                CP_ASYNC16(sb + bnext + doff, (const void*)(g_Whi + gsrc));
                CP_ASYNC16(sb + bnext + PR_ATILE + doff, (const void*)(g_Wlo + gsrc));
            }
            CP_COMMIT();
        }

        // ---- 4. MMA on A + B[c] ----
#pragma unroll
        for (int kk = 0; kk < 4; kk++) {
            uint32_t ah0, ah1, ah2, ah3, al0, al1, al2, al3;
            ldsm_x4(sb + PR_A + a_off + kk * 32, ah0, ah1, ah2, ah3);
            ldsm_x4(sb + PR_A + PR_ATILE + a_off + kk * 32, al0, al1, al2, al3);
#pragma unroll
            for (int np = 0; np < 8; np++) {
                uint32_t bh0, bh1, bh2, bh3, bl0, bl1, bl2, bl3;
                uint32_t boff = b_off + (uint32_t)(np * 16) * PR_ROWB + kk * 32;
                ldsm_x4(sb + bbuf + boff, bh0, bh1, bh2, bh3);
                ldsm_x4(sb + bbuf + PR_ATILE + boff, bl0, bl1, bl2, bl3);
                int t0 = 2 * np, t1 = t0 + 1;
                mma_bf16(o[t0][0], o[t0][1], o[t0][2], o[t0][3], ah0, ah1, ah2, ah3, bh0, bh1);
                mma_bf16(o[t1][0], o[t1][1], o[t1][2], o[t1][3], ah0, ah1, ah2, ah3, bh2, bh3);
                mma_bf16(o[t0][0], o[t0][1], o[t0][2], o[t0][3], ah0, ah1, ah2, ah3, bl0, bl1);
                mma_bf16(o[t1][0], o[t1][1], o[t1][2], o[t1][3], ah0, ah1, ah2, ah3, bl2, bl3);
                mma_bf16(o[t0][0], o[t0][1], o[t0][2], o[t0][3], al0, al1, al2, al3, bh0, bh1);
                mma_bf16(o[t1][0], o[t1][1], o[t1][2], o[t1][3], al0, al1, al2, al3, bh2, bh3);
            }
        }

        // ---- 5. protect A before next overwrite ----
        __syncthreads();
    }

    // ---- epilogue: split result, write bf16 hi/lo; Q scaled by 1/32 ----
    const float scale = (which == 1) ? 0.03125f : 1.0f;
    __nv_bfloat16* dh = (which == 0) ? g_Khi : (which == 1) ? g_Qhi : g_Vhi;
    __nv_bfloat16* dl = (which == 0) ? g_Klo : (which == 1) ? g_Qlo : g_Vlo;
    const int r0 = m0 + w * 16 + (lane >> 2);
    const int r1 = r0 + 8;
#pragma unroll
    for (int nt = 0; nt < 16; nt++) {
        int col = nt * 8 + 2 * (lane & 3);
        uint32_t hi, lo;
        split2(o[nt][0] * scale, o[nt][1] * scale, hi, lo);
        *(uint32_t*)(dh + (size_t)r0 * HDIM + col) = hi;
        *(uint32_t*)(dl + (size_t)r0 * HDIM + col) = lo;
        split2(o[nt][2] * scale, o[nt][3] * scale, hi, lo);
        *(uint32_t*)(dh + (size_t)r1 * HDIM + col) = hi;
        *(uint32_t*)(dl + (size_t)r1 * HDIM + col) = lo;
    }
}

// ===========================================================================
// Flash attention via mma.sync bf16-split (4 warps, 128 threads),
// Q fragments hoisted into registers for the whole key loop.
// grid (32 pairs, 4 batch). BQ=64, BK=64, pair balancing (65 iters/CTA).
// ===========================================================================
#define AT_ROWB 272               // 128 bf16 = 256B + 16B pad
#define AT_TILE 17408             // 64*272
#define AT_QHI  0
#define AT_QLO  17408
#define AT_KV   34816             // + buf*69632 : KHI,KLO,VHI,VLO
#define AT_BUF  69632
#define AT_SMEM 174080

__device__ __forceinline__ void prefetch_kv(uint32_t sb_buf, int grow, int tid)
{
#pragma unroll
    for (int t = 0; t < 4; t++) {
        const __nv_bfloat16* g =
            (t == 0) ? g_Khi : (t == 1) ? g_Klo : (t == 2) ? g_Vhi : g_Vlo;
        g += (size_t)grow * HDIM;
        uint32_t tb = sb_buf + t * AT_TILE;
#pragma unroll
        for (int j = 0; j < 8; j++) {
            int idx = tid + j * 128;
            int row = idx >> 4, c16 = idx & 15;
            uint32_t dst = tb + (uint32_t)row * AT_ROWB + (uint32_t)c16 * 16;
            CP_ASYNC16(dst, (const void*)(g + (size_t)row * HDIM + c16 * 8));
        }
    }
    CP_COMMIT();
}

__global__ __launch_bounds__(128) void attn_mma_kernel(float* __restrict__ out)
{
    char* smem = dsmem;
    uint32_t sb = smem_to_u32(smem);
    const int tid  = threadIdx.x;
    const int lane = tid & 31;
    const int w    = tid >> 5;
    const int b    = blockIdx.y;
    const int pair = blockIdx.x;
    const int bbase = b * SEQ;

    // ldmatrix lane offsets
    const uint32_t a_off = (uint32_t)(w * 16 + (lane & 15)) * AT_ROWB
                         + (uint32_t)((lane >> 4) << 3) * 2;
    const uint32_t b_off = (uint32_t)((lane & 7) + ((lane >> 4) << 3)) * AT_ROWB
                         + (uint32_t)(((lane >> 3) & 1) << 3) * 2;
    const uint32_t v_off = (uint32_t)((lane & 7) + (((lane >> 3) & 1) << 3)) * AT_ROWB
                         + (uint32_t)((lane >> 4) << 3) * 2;

    for (int half = 0; half < 2; half++) {
        const int qt = half ? (63 - pair) : pair;
        const int nkt = qt + 1;

        // ---- stage Q tile (hi/lo) into smem ----
        __syncthreads();
        {
            const size_t gq = (size_t)(bbase + qt * 64) * HDIM;
#pragma unroll
            for (int j = 0; j < 8; j++) {
                int idx = tid + j * 128;
                int row = idx >> 4, c16 = idx & 15;
                uint32_t doff = (uint32_t)row * AT_ROWB + (uint32_t)c16 * 16;
                *(uint4*)(smem + AT_QHI + doff) =
                    *(const uint4*)(g_Qhi + gq + (size_t)row * HDIM + c16 * 8);
                *(uint4*)(smem + AT_QLO + doff) =
                    *(const uint4*)(g_Qlo + gq + (size_t)row * HDIM + c16 * 8);
            }
        }
        __syncthreads();

        // ---- hoist Q fragments into registers (invariant over key loop) ----
        uint32_t qh[8][4], ql[8][4];
#pragma unroll
        for (int kk = 0; kk < 8; kk++) {
            ldsm_x4(sb + AT_QHI + a_off + kk * 32,
                    qh[kk][0], qh[kk][1], qh[kk][2], qh[kk][3]);
            ldsm_x4(sb + AT_QLO + a_off + kk * 32,
                    ql[kk][0], ql[kk][1], ql[kk][2], ql[kk][3]);
        }

        float o[16][4];
#pragma unroll
        for (int t = 0; t < 16; t++)
#pragma unroll
            for (int k = 0; k < 4; k++) o[t][k] = 0.0f;
        float m0 = -INFINITY, m1 = -INFINITY, l0 = 0.0f, l1 = 0.0f;

        prefetch_kv(sb + AT_KV, bbase, tid);   // kt = 0 into buf 0

        for (int kt = 0; kt < nkt; kt++) {
            CP_WAIT0();
            __syncthreads();
            if (kt + 1 < nkt)
                prefetch_kv(sb + AT_KV + ((kt + 1) & 1) * AT_BUF,
                            bbase + (kt + 1) * 64, tid);
            const uint32_t kb = sb + AT_KV + (kt & 1) * AT_BUF;

            // ---- S = Q K^T (3-product split), Q from registers ----
            float s[8][4];
#pragma unroll
            for (int t = 0; t < 8; t++)
#pragma unroll
                for (int k = 0; k < 4; k++) s[t][k] = 0.0f;

#pragma unroll
            for (int kk = 0; kk < 8; kk++) {
#pragma unroll
                for (int np = 0; np < 4; np++) {
                    uint32_t kh0, kh1, kh2, kh3, kl0, kl1, kl2, kl3;
                    uint32_t boff = b_off + (uint32_t)(np * 16) * AT_ROWB + kk * 32;
                    ldsm_x4(kb + 0 * AT_TILE + boff, kh0, kh1, kh2, kh3);
                    ldsm_x4(kb + 1 * AT_TILE + boff, kl0, kl1, kl2, kl3);
                    int t0 = 2 * np, t1 = t0 + 1;
                    mma_bf16(s[t0][0], s[t0][1], s[t0][2], s[t0][3],
                             qh[kk][0], qh[kk][1], qh[kk][2], qh[kk][3], kh0, kh1);
                    mma_bf16(s[t1][0], s[t1][1], s[t1][2], s[t1][3],
                             qh[kk][0], qh[kk][1], qh[kk][2], qh[kk][3], kh2, kh3);
                    mma_bf16(s[t0][0], s[t0][1], s[t0][2], s[t0][3],
                             qh[kk][0], qh[kk][1], qh[kk][2], qh[kk][3], kl0, kl1);
                    mma_bf16(s[t1][0], s[t1][1], s[t1][2], s[t1][3],
                             qh[kk][0], qh[kk][1], qh[kk][2], qh[kk][3], kl2, kl3);
                    mma_bf16(s[t0][0], s[t0][1], s[t0][2], s[t0][3],
                             ql[kk][0], ql[kk][1], ql[kk][2], ql[kk][3], kh0, kh1);
                    mma_bf16(s[t1][0], s[t1][1], s[t1][2], s[t1][3],
                             ql[kk][0], ql[kk][1], ql[kk][2], ql[kk][3], kh2, kh3);
                }
            }

            // ---- causal mask on diagonal tile ----
            if (kt == qt) {
                const int r0 = w * 16 + (lane >> 2);
                const int r1 = r0 + 8;
#pragma unroll
                for (int nt = 0; nt < 8; nt++) {
                    int c = nt * 8 + 2 * (lane & 3);
                    if (c     > r0) s[nt][0] = -INFINITY;
                    if (c + 1 > r0) s[nt][1] = -INFINITY;
                    if (c     > r1) s[nt][2] = -INFINITY;
                    if (c + 1 > r1) s[nt][3] = -INFINITY;
                }
            }

            // ---- online softmax (per-warp rows; quad reduce over cols) ----
            float rmax0 = -INFINITY, rmax1 = -INFINITY;
#pragma unroll
            for (int nt = 0; nt < 8; nt++) {
                rmax0 = fmaxf(rmax0, fmaxf(s[nt][0], s[nt][1]));
                rmax1 = fmaxf(rmax1, fmaxf(s[nt][2], s[nt][3]));
            }
            rmax0 = fmaxf(rmax0, __shfl_xor_sync(0xffffffffu, rmax0, 1));
            rmax0 = fmaxf(rmax0, __shfl_xor_sync(0xffffffffu, rmax0, 2));
            rmax1 = fmaxf(rmax1, __shfl_xor_sync(0xffffffffu, rmax1, 1));
            rmax1 = fmaxf(rmax1, __shfl_xor_sync(0xffffffffu, rmax1, 2));

            float mn0 = fmaxf(m0, rmax0), mn1 = fmaxf(m1, rmax1);
            float alpha0 = __expf(m0 - mn0), alpha1 = __expf(m1 - mn1);
            m0 = mn0; m1 = mn1;

            float sum0 = 0.0f, sum1 = 0.0f;
#pragma unroll
            for (int nt = 0; nt < 8; nt++) {
                s[nt][0] = __expf(s[nt][0] - mn0);
                s[nt][1] = __expf(s[nt][1] - mn0);
                s[nt][2] = __expf(s[nt][2] - mn1);
                s[nt][3] = __expf(s[nt][3] - mn1);
                sum0 += s[nt][0] + s[nt][1];
                sum1 += s[nt][2] + s[nt][3];
            }
            sum0 += __shfl_xor_sync(0xffffffffu, sum0, 1);
            sum0 += __shfl_xor_sync(0xffffffffu, sum0, 2);
            sum1 += __shfl_xor_sync(0xffffffffu, sum1, 1);
            sum1 += __shfl_xor_sync(0xffffffffu, sum1, 2);
            l0 = l0 * alpha0 + sum0;
            l1 = l1 * alpha1 + sum1;

#pragma unroll
            for (int t = 0; t < 16; t++) {
                o[t][0] *= alpha0; o[t][1] *= alpha0;
                o[t][2] *= alpha1; o[t][3] *= alpha1;
            }

            // ---- O += P V (P frag built by register remap, split) ----
#pragma unroll
            for (int kk2 = 0; kk2 < 4; kk2++) {
                int t0 = 2 * kk2, t1 = t0 + 1;
                uint32_t ah0, ah1, ah2, ah3, al0, al1, al2, al3;
                split2(s[t0][0], s[t0][1], ah0, al0);
                split2(s[t0][2], s[t0][3], ah1, al1);
                split2(s[t1][0], s[t1][1], ah2, al2);
                split2(s[t1][2], s[t1][3], ah3, al3);
#pragma unroll
                for (int np = 0; np < 8; np++) {
                    uint32_t vh0, vh1, vh2, vh3, vl0, vl1, vl2, vl3;
                    uint32_t voff = v_off + (uint32_t)(kk2 * 16) * AT_ROWB + np * 32;
                    ldsm_x4_t(kb + 2 * AT_TILE + voff, vh0, vh1, vh2, vh3);
                    ldsm_x4_t(kb + 3 * AT_TILE + voff, vl0, vl1, vl2, vl3);
                    int u0 = 2 * np, u1 = u0 + 1;
                    mma_bf16(o[u0][0], o[u0][1], o[u0][2], o[u0][3], ah0, ah1, ah2, ah3, vh0, vh1);
                    mma_bf16(o[u1][0], o[u1][1], o[u1][2], o[u1][3], ah0, ah1, ah2, ah3, vh2, vh3);
                    mma_bf16(o[u0][0], o[u0][1], o[u0][2], o[u0][3], ah0, ah1, ah2, ah3, vl0, vl1);
                    mma_bf16(o[u1][0], o[u1][1], o[u1][2], o[u1][3], ah0, ah1, ah2, ah3, vl2, vl3);
                    mma_bf16(o[u0][0], o[u0][1], o[u0][2], o[u0][3], al0, al1, al2, al3, vh0, vh1);
                    mma_bf16(o[u1][0], o[u1][1], o[u1][2], o[u1][3], al0, al1, al2, al3, vh2, vh3);
                }
            }
        }

        // ---- epilogue: normalize, store fp32 ----
        const float inv0 = 1.0f / l0, inv1 = 1.0f / l1;
        const int gr0 = bbase + qt * 64 + w * 16 + (lane >> 2);
        const int gr1 = gr0 + 8;
#pragma unroll
        for (int nt = 0; nt < 16; nt++) {
            int col = nt * 8 + 2 * (lane & 3);
            *(float2*)(out + (size_t)gr0 * HDIM + col) =
                make_float2(o[nt][0] * inv0, o[nt][1] * inv0);
            *(float2*)(out + (size_t)gr1 * HDIM + col) =
                make_float2(o[nt][2] * inv1, o[nt][3] * inv1);
        }
    }
}

// ---------------------------------------------------------------------------
extern "C" void kernel_launch(void* const* d_in, const int* in_sizes, int n_in,
                              void* d_out, int out_size)
{
    const float* x  = (const float*)d_in[0];
    const float* Wk = (const float*)d_in[1];
    const float* Wq = (const float*)d_in[2];
    const float* Wv = (const float*)d_in[3];
    float* out = (float*)d_out;

    static bool attr_set = false;
    if (!attr_set) {
        cudaFuncSetAttribute(proj_mma_kernel,
                             cudaFuncAttributeMaxDynamicSharedMemorySize, PR_SMEM);
        cudaFuncSetAttribute(attn_mma_kernel,
                             cudaFuncAttributeMaxDynamicSharedMemorySize, AT_SMEM);
        attr_set = true;
    }

    // 1) split weights to bf16 hi/lo
    wsplit_kernel<<<(3 * HDIM * EMB + 255) / 256, 256>>>(Wk, Wq, Wv);

    // 2) Q/K/V projections on tensor cores (bf16-split), B pipelined, 2 CTA/SM
    proj_mma_kernel<<<dim3(128, 3), 256, PR_SMEM>>>(x);

    // 3) causal flash attention on tensor cores (bf16-split), Q in registers
    attn_mma_kernel<<<dim3(32, BATCH), 128, AT_SMEM>>>(out);
}

// round 8
// speedup vs baseline: 1.0744x; 1.0744x over previous
#include <cuda_runtime.h>
#include <cuda_bf16.h>
#include <math.h>
#include <cstdint>

#define BATCH 4
#define SEQ   4096
#define EMB   1024
#define HDIM  128

// ---------------------------------------------------------------------------
// scratch (allocation-free: __device__ globals) — all bf16 hi/lo split pairs
// ---------------------------------------------------------------------------
__device__ __nv_bfloat16 g_Qhi[(size_t)BATCH * SEQ * HDIM];
__device__ __nv_bfloat16 g_Qlo[(size_t)BATCH * SEQ * HDIM];
__device__ __nv_bfloat16 g_Khi[(size_t)BATCH * SEQ * HDIM];
__device__ __nv_bfloat16 g_Klo[(size_t)BATCH * SEQ * HDIM];
__device__ __nv_bfloat16 g_Vhi[(size_t)BATCH * SEQ * HDIM];
__device__ __nv_bfloat16 g_Vlo[(size_t)BATCH * SEQ * HDIM];
// split weights: [which][HDIM][EMB], which: 0=K,1=Q,2=V
__device__ __nv_bfloat16 g_Whi[3 * HDIM * EMB];
__device__ __nv_bfloat16 g_Wlo[3 * HDIM * EMB];

// ===========================================================================
// mma.sync / ldmatrix / cp.async helpers (baseline PTX, no 'a' features)
// ===========================================================================
__device__ __forceinline__ uint32_t smem_to_u32(const void* p) {
    uint32_t a;
    asm("{ .reg .u64 t; cvta.to.shared.u64 t, %1; cvt.u32.u64 %0, t; }"
        : "=r"(a) : "l"(p));
    return a;
}

__device__ __forceinline__ void ldsm_x4(uint32_t addr,
    uint32_t& r0, uint32_t& r1, uint32_t& r2, uint32_t& r3) {
    asm volatile("ldmatrix.sync.aligned.m8n8.x4.shared.b16 {%0,%1,%2,%3}, [%4];"
        : "=r"(r0), "=r"(r1), "=r"(r2), "=r"(r3) : "r"(addr));
}

__device__ __forceinline__ void ldsm_x4_t(uint32_t addr,
    uint32_t& r0, uint32_t& r1, uint32_t& r2, uint32_t& r3) {
    asm volatile("ldmatrix.sync.aligned.m8n8.x4.trans.shared.b16 {%0,%1,%2,%3}, [%4];"
        : "=r"(r0), "=r"(r1), "=r"(r2), "=r"(r3) : "r"(addr));
}

__device__ __forceinline__ void mma_bf16(float& c0, float& c1, float& c2, float& c3,
    uint32_t a0, uint32_t a1, uint32_t a2, uint32_t a3, uint32_t b0, uint32_t b1) {
    asm volatile(
        "mma.sync.aligned.m16n8k16.row.col.f32.bf16.bf16.f32 "
        "{%0,%1,%2,%3}, {%4,%5,%6,%7}, {%8,%9}, {%0,%1,%2,%3};"
        : "+f"(c0), "+f"(c1), "+f"(c2), "+f"(c3)
        : "r"(a0), "r"(a1), "r"(a2), "r"(a3), "r"(b0), "r"(b1));
}

#define CP_ASYNC16(dst, src) \
    asm volatile("cp.async.cg.shared.global [%0], [%1], 16;" :: "r"(dst), "l"(src))
#define CP_COMMIT()  asm volatile("cp.async.commit_group;" ::: "memory")
#define CP_WAIT0()   asm volatile("cp.async.wait_group 0;" ::: "memory")

// pack two floats into bf16x2 hi + residual lo
__device__ __forceinline__ void split2(float x0, float x1, uint32_t& hi, uint32_t& lo) {
    __nv_bfloat16 h0 = __float2bfloat16(x0);
    __nv_bfloat16 h1 = __float2bfloat16(x1);
    __nv_bfloat16 g0 = __float2bfloat16(x0 - __bfloat162float(h0));
    __nv_bfloat16 g1 = __float2bfloat16(x1 - __bfloat162float(h1));
    hi = (uint32_t)__bfloat16_as_ushort(h0) | ((uint32_t)__bfloat16_as_ushort(h1) << 16);
    lo = (uint32_t)__bfloat16_as_ushort(g0) | ((uint32_t)__bfloat16_as_ushort(g1) << 16);
}

// ===========================================================================
// Weight split prepass: W (fp32) -> (hi, lo) bf16
// ===========================================================================
__global__ __launch_bounds__(256) void wsplit_kernel(
    const float* __restrict__ Wk,
    const float* __restrict__ Wq,
    const float* __restrict__ Wv)
{
    int idx = blockIdx.x * 256 + threadIdx.x;
    if (idx >= 3 * HDIM * EMB) return;
    int which = idx >> 17;
    int within = idx & ((HDIM * EMB) - 1);
    const float* W = (which == 0) ? Wk : (which == 1) ? Wq : Wv;
    float w = W[within];
    __nv_bfloat16 hi = __float2bfloat16(w);
    __nv_bfloat16 lo = __float2bfloat16(w - __bfloat162float(hi));
    g_Whi[idx] = hi;
    g_Wlo[idx] = lo;
}

// ===========================================================================
// Projection GEMM via mma.sync bf16-split — R3 version (73728 B smem,
// 3 CTAs/SM; synchronous loads hidden by cross-CTA TLP).
// grid (128 m-tiles, 3 heads), 256 threads (8 warps x 16 rows = 128 rows).
// ===========================================================================
#define PR_ROWB 144               // 64 bf16 = 128B + 16B pad
#define PR_AHI  0
#define PR_ALO  18432             // 128*144
#define PR_BHI  36864
#define PR_BLO  55296
#define PR_SMEM 73728

extern __shared__ char dsmem[];

__global__ __launch_bounds__(256) void proj_mma_kernel(const float* __restrict__ x)
{
    char* smem = dsmem;
    uint32_t sb = smem_to_u32(smem);
    const int tid  = threadIdx.x;
    const int lane = tid & 31;
    const int w    = tid >> 5;
    const int m0   = blockIdx.x * 128;
    const int which = blockIdx.y;

    // ldmatrix lane offsets
    const uint32_t a_off = (uint32_t)(w * 16 + (lane & 15)) * PR_ROWB
                         + (uint32_t)((lane >> 4) << 3) * 2;
    const uint32_t b_off = (uint32_t)((lane & 7) + ((lane >> 4) << 3)) * PR_ROWB
                         + (uint32_t)(((lane >> 3) & 1) << 3) * 2;

    float o[16][4];
#pragma unroll
    for (int t = 0; t < 16; t++)
#pragma unroll
        for (int k = 0; k < 4; k++) o[t][k] = 0.0f;

    const int a_row  = tid >> 1;
    const int a_half = tid & 1;

    for (int e0 = 0; e0 < EMB; e0 += 64) {
        __syncthreads();
        // ---- A: load x fp32, split to bf16 hi/lo ----
        {
            const float* xr = x + (size_t)(m0 + a_row) * EMB + e0 + a_half * 32;
            uint32_t abase = (uint32_t)a_row * PR_ROWB + (uint32_t)(a_half * 32) * 2;
#pragma unroll
            for (int i = 0; i < 8; i++) {
                float4 v = *(const float4*)(xr + i * 4);
                uint32_t h01, l01, h23, l23;
                split2(v.x, v.y, h01, l01);
                split2(v.z, v.w, h23, l23);
                uint32_t off = abase + (uint32_t)(i * 4) * 2;
                *(uint32_t*)(smem + PR_AHI + off)     = h01;
                *(uint32_t*)(smem + PR_AHI + off + 4) = h23;
                *(uint32_t*)(smem + PR_ALO + off)     = l01;
                *(uint32_t*)(smem + PR_ALO + off + 4) = l23;
            }
        }
        // ---- B: copy pre-split W tiles ----
#pragma unroll
        for (int j = 0; j < 4; j++) {
            int idx = tid + j * 256;          // 0..1023
            int row = idx >> 3, c8 = idx & 7;
            size_t gsrc = (size_t)(which * HDIM + row) * EMB + e0 + c8 * 8;
            uint32_t doff = (uint32_t)row * PR_ROWB + (uint32_t)c8 * 16;
            *(uint4*)(smem + PR_BHI + doff) = *(const uint4*)(g_Whi + gsrc);
            *(uint4*)(smem + PR_BLO + doff) = *(const uint4*)(g_Wlo + gsrc);
        }
        __syncthreads();

        // ---- MMA ----
#pragma unroll
        for (int kk = 0; kk < 4; kk++) {
            uint32_t ah0, ah1, ah2, ah3, al0, al1, al2, al3;
            ldsm_x4(sb + PR_AHI + a_off + kk * 32, ah0, ah1, ah2, ah3);
            ldsm_x4(sb + PR_ALO + a_off + kk * 32, al0, al1, al2, al3);
#pragma unroll
            for (int np = 0; np < 8; np++) {
                uint32_t bh0, bh1, bh2, bh3, bl0, bl1, bl2, bl3;
                uint32_t boff = b_off + (uint32_t)(np * 16) * PR_ROWB + kk * 32;
                ldsm_x4(sb + PR_BHI + boff, bh0, bh1, bh2, bh3);
                ldsm_x4(sb + PR_BLO + boff, bl0, bl1, bl2, bl3);
                int t0 = 2 * np, t1 = t0 + 1;
                mma_bf16(o[t0][0], o[t0][1], o[t0][2], o[t0][3], ah0, ah1, ah2, ah3, bh0, bh1);
                mma_bf16(o[t0][0], o[t0][1], o[t0][2], o[t0][3], ah0, ah1, ah2, ah3, bl0, bl1);
                mma_bf16(o[t0][0], o[t0][1], o[t0][2], o[t0][3], al0, al1, al2, al3, bh0, bh1);
                mma_bf16(o[t1][0], o[t1][1], o[t1][2], o[t1][3], ah0, ah1, ah2, ah3, bh2, bh3);
                mma_bf16(o[t1][0], o[t1][1], o[t1][2], o[t1][3], ah0, ah1, ah2, ah3, bl2, bl3);
                mma_bf16(o[t1][0], o[t1][1], o[t1][2], o[t1][3], al0, al1, al2, al3, bh2, bh3);
            }
        }
    }

    // ---- epilogue: split result, write bf16 hi/lo; Q scaled by 1/32 ----
    const float scale = (which == 1) ? 0.03125f : 1.0f;
    __nv_bfloat16* dh = (which == 0) ? g_Khi : (which == 1) ? g_Qhi : g_Vhi;
    __nv_bfloat16* dl = (which == 0) ? g_Klo : (which == 1) ? g_Qlo : g_Vlo;
    const int r0 = m0 + w * 16 + (lane >> 2);
    const int r1 = r0 + 8;
#pragma unroll
    for (int nt = 0; nt < 16; nt++) {
        int col = nt * 8 + 2 * (lane & 3);
        uint32_t hi, lo;
        split2(o[nt][0] * scale, o[nt][1] * scale, hi, lo);
        *(uint32_t*)(dh + (size_t)r0 * HDIM + col) = hi;
        *(uint32_t*)(dl + (size_t)r0 * HDIM + col) = lo;
        split2(o[nt][2] * scale, o[nt][3] * scale, hi, lo);
        *(uint32_t*)(dh + (size_t)r1 * HDIM + col) = hi;
        *(uint32_t*)(dl + (size_t)r1 * HDIM + col) = lo;
    }
}

// ===========================================================================
// Flash attention via mma.sync bf16-split (4 warps, 128 threads),
// Q fragments hoisted into registers for the whole key loop.
// grid (32 pairs, 4 batch). BQ=64, BK=64, pair balancing (65 iters/CTA).
// ===========================================================================
#define AT_ROWB 272               // 128 bf16 = 256B + 16B pad
#define AT_TILE 17408             // 64*272
#define AT_QHI  0
#define AT_QLO  17408
#define AT_KV   34816             // + buf*69632 : KHI,KLO,VHI,VLO
#define AT_BUF  69632
#define AT_SMEM 174080

__device__ __forceinline__ void prefetch_kv(uint32_t sb_buf, int grow, int tid)
{
#pragma unroll
    for (int t = 0; t < 4; t++) {
        const __nv_bfloat16* g =
            (t == 0) ? g_Khi : (t == 1) ? g_Klo : (t == 2) ? g_Vhi : g_Vlo;
        g += (size_t)grow * HDIM;
        uint32_t tb = sb_buf + t * AT_TILE;
#pragma unroll
        for (int j = 0; j < 8; j++) {
            int idx = tid + j * 128;
            int row = idx >> 4, c16 = idx & 15;
            uint32_t dst = tb + (uint32_t)row * AT_ROWB + (uint32_t)c16 * 16;
            CP_ASYNC16(dst, (const void*)(g + (size_t)row * HDIM + c16 * 8));
        }
    }
    CP_COMMIT();
}

__global__ __launch_bounds__(128) void attn_mma_kernel(float* __restrict__ out)
{
    char* smem = dsmem;
    uint32_t sb = smem_to_u32(smem);
    const int tid  = threadIdx.x;
    const int lane = tid & 31;
    const int w    = tid >> 5;
    const int b    = blockIdx.y;
    const int pair = blockIdx.x;
    const int bbase = b * SEQ;

    // ldmatrix lane offsets
    const uint32_t a_off = (uint32_t)(w * 16 + (lane & 15)) * AT_ROWB
                         + (uint32_t)((lane >> 4) << 3) * 2;
    const uint32_t b_off = (uint32_t)((lane & 7) + ((lane >> 4) << 3)) * AT_ROWB
                         + (uint32_t)(((lane >> 3) & 1) << 3) * 2;
    const uint32_t v_off = (uint32_t)((lane & 7) + (((lane >> 3) & 1) << 3)) * AT_ROWB
                         + (uint32_t)((lane >> 4) << 3) * 2;

    for (int half = 0; half < 2; half++) {
        const int qt = half ? (63 - pair) : pair;
        const int nkt = qt + 1;

        // ---- stage Q tile (hi/lo) into smem ----
        __syncthreads();
        {
            const size_t gq = (size_t)(bbase + qt * 64) * HDIM;
#pragma unroll
            for (int j = 0; j < 8; j++) {
                int idx = tid + j * 128;
                int row = idx >> 4, c16 = idx & 15;
                uint32_t doff = (uint32_t)row * AT_ROWB + (uint32_t)c16 * 16;
                *(uint4*)(smem + AT_QHI + doff) =
                    *(const uint4*)(g_Qhi + gq + (size_t)row * HDIM + c16 * 8);
                *(uint4*)(smem + AT_QLO + doff) =
                    *(const uint4*)(g_Qlo + gq + (size_t)row * HDIM + c16 * 8);
            }
        }
        __syncthreads();

        // ---- hoist Q fragments into registers (invariant over key loop) ----
        uint32_t qh[8][4], ql[8][4];
#pragma unroll
        for (int kk = 0; kk < 8; kk++) {
            ldsm_x4(sb + AT_QHI + a_off + kk * 32,
                    qh[kk][0], qh[kk][1], qh[kk][2], qh[kk][3]);
            ldsm_x4(sb + AT_QLO + a_off + kk * 32,
                    ql[kk][0], ql[kk][1], ql[kk][2], ql[kk][3]);
        }

        float o[16][4];
#pragma unroll
        for (int t = 0; t < 16; t++)
#pragma unroll
            for (int k = 0; k < 4; k++) o[t][k] = 0.0f;
        float m0 = -INFINITY, m1 = -INFINITY, l0 = 0.0f, l1 = 0.0f;

        prefetch_kv(sb + AT_KV, bbase, tid);   // kt = 0 into buf 0

        for (int kt = 0; kt < nkt; kt++) {
            CP_WAIT0();
            __syncthreads();
            if (kt + 1 < nkt)
                prefetch_kv(sb + AT_KV + ((kt + 1) & 1) * AT_BUF,
                            bbase + (kt + 1) * 64, tid);
            const uint32_t kb = sb + AT_KV + (kt & 1) * AT_BUF;

            // ---- S = Q K^T (3-product split), Q from registers ----
            float s[8][4];
#pragma unroll
            for (int t = 0; t < 8; t++)
#pragma unroll
                for (int k = 0; k < 4; k++) s[t][k] = 0.0f;

#pragma unroll
            for (int kk = 0; kk < 8; kk++) {
#pragma unroll
                for (int np = 0; np < 4; np++) {
                    uint32_t kh0, kh1, kh2, kh3, kl0, kl1, kl2, kl3;
                    uint32_t boff = b_off + (uint32_t)(np * 16) * AT_ROWB + kk * 32;
                    ldsm_x4(kb + 0 * AT_TILE + boff, kh0, kh1, kh2, kh3);
                    ldsm_x4(kb + 1 * AT_TILE + boff, kl0, kl1, kl2, kl3);
                    int t0 = 2 * np, t1 = t0 + 1;
                    mma_bf16(s[t0][0], s[t0][1], s[t0][2], s[t0][3],
                             qh[kk][0], qh[kk][1], qh[kk][2], qh[kk][3], kh0, kh1);
                    mma_bf16(s[t1][0], s[t1][1], s[t1][2], s[t1][3],
                             qh[kk][0], qh[kk][1], qh[kk][2], qh[kk][3], kh2, kh3);
                    mma_bf16(s[t0][0], s[t0][1], s[t0][2], s[t0][3],
                             qh[kk][0], qh[kk][1], qh[kk][2], qh[kk][3], kl0, kl1);
                    mma_bf16(s[t1][0], s[t1][1], s[t1][2], s[t1][3],
                             qh[kk][0], qh[kk][1], qh[kk][2], qh[kk][3], kl2, kl3);
                    mma_bf16(s[t0][0], s[t0][1], s[t0][2], s[t0][3],
                             ql[kk][0], ql[kk][1], ql[kk][2], ql[kk][3], kh0, kh1);
                    mma_bf16(s[t1][0], s[t1][1], s[t1][2], s[t1][3],
                             ql[kk][0], ql[kk][1], ql[kk][2], ql[kk][3], kh2, kh3);
                }
            }

            // ---- causal mask on diagonal tile ----
            if (kt == qt) {
                const int r0 = w * 16 + (lane >> 2);
                const int r1 = r0 + 8;
#pragma unroll
                for (int nt = 0; nt < 8; nt++) {
                    int c = nt * 8 + 2 * (lane & 3);
                    if (c     > r0) s[nt][0] = -INFINITY;
                    if (c + 1 > r0) s[nt][1] = -INFINITY;
                    if (c     > r1) s[nt][2] = -INFINITY;
                    if (c + 1 > r1) s[nt][3] = -INFINITY;
                }
            }

            // ---- online softmax (per-warp rows; quad reduce over cols) ----
            float rmax0 = -INFINITY, rmax1 = -INFINITY;
#pragma unroll
            for (int nt = 0; nt < 8; nt++) {
                rmax0 = fmaxf(rmax0, fmaxf(s[nt][0], s[nt][1]));
                rmax1 = fmaxf(rmax1, fmaxf(s[nt][2], s[nt][3]));
            }
            rmax0 = fmaxf(rmax0, __shfl_xor_sync(0xffffffffu, rmax0, 1));
            rmax0 = fmaxf(rmax0, __shfl_xor_sync(0xffffffffu, rmax0, 2));
            rmax1 = fmaxf(rmax1, __shfl_xor_sync(0xffffffffu, rmax1, 1));
            rmax1 = fmaxf(rmax1, __shfl_xor_sync(0xffffffffu, rmax1, 2));

            float mn0 = fmaxf(m0, rmax0), mn1 = fmaxf(m1, rmax1);
            float alpha0 = __expf(m0 - mn0), alpha1 = __expf(m1 - mn1);
            m0 = mn0; m1 = mn1;

            float sum0 = 0.0f, sum1 = 0.0f;
#pragma unroll
            for (int nt = 0; nt < 8; nt++) {
                s[nt][0] = __expf(s[nt][0] - mn0);
                s[nt][1] = __expf(s[nt][1] - mn0);
                s[nt][2] = __expf(s[nt][2] - mn1);
                s[nt][3] = __expf(s[nt][3] - mn1);
                sum0 += s[nt][0] + s[nt][1];
                sum1 += s[nt][2] + s[nt][3];
            }
            sum0 += __shfl_xor_sync(0xffffffffu, sum0, 1);
            sum0 += __shfl_xor_sync(0xffffffffu, sum0, 2);
            sum1 += __shfl_xor_sync(0xffffffffu, sum1, 1);
            sum1 += __shfl_xor_sync(0xffffffffu, sum1, 2);
            l0 = l0 * alpha0 + sum0;
            l1 = l1 * alpha1 + sum1;

#pragma unroll
            for (int t = 0; t < 16; t++) {
                o[t][0] *= alpha0; o[t][1] *= alpha0;
                o[t][2] *= alpha1; o[t][3] *= alpha1;
            }

            // ---- O += P V (P frag built by register remap, split) ----
#pragma unroll
            for (int kk2 = 0; kk2 < 4; kk2++) {
                int t0 = 2 * kk2, t1 = t0 + 1;
                uint32_t ah0, ah1, ah2, ah3, al0, al1, al2, al3;
                split2(s[t0][0], s[t0][1], ah0, al0);
                split2(s[t0][2], s[t0][3], ah1, al1);
                split2(s[t1][0], s[t1][1], ah2, al2);
                split2(s[t1][2], s[t1][3], ah3, al3);
#pragma unroll
                for (int np = 0; np < 8; np++) {
                    uint32_t vh0, vh1, vh2, vh3, vl0, vl1, vl2, vl3;
                    uint32_t voff = v_off + (uint32_t)(kk2 * 16) * AT_ROWB + np * 32;
                    ldsm_x4_t(kb + 2 * AT_TILE + voff, vh0, vh1, vh2, vh3);
                    ldsm_x4_t(kb + 3 * AT_TILE + voff, vl0, vl1, vl2, vl3);
                    int u0 = 2 * np, u1 = u0 + 1;
                    mma_bf16(o[u0][0], o[u0][1], o[u0][2], o[u0][3], ah0, ah1, ah2, ah3, vh0, vh1);
                    mma_bf16(o[u1][0], o[u1][1], o[u1][2], o[u1][3], ah0, ah1, ah2, ah3, vh2, vh3);
                    mma_bf16(o[u0][0], o[u0][1], o[u0][2], o[u0][3], ah0, ah1, ah2, ah3, vl0, vl1);
                    mma_bf16(o[u1][0], o[u1][1], o[u1][2], o[u1][3], ah0, ah1, ah2, ah3, vl2, vl3);
                    mma_bf16(o[u0][0], o[u0][1], o[u0][2], o[u0][3], al0, al1, al2, al3, vh0, vh1);
                    mma_bf16(o[u1][0], o[u1][1], o[u1][2], o[u1][3], al0, al1, al2, al3, vh2, vh3);
                }
            }
        }

        // ---- epilogue: normalize, store fp32 ----
        const float inv0 = 1.0f / l0, inv1 = 1.0f / l1;
        const int gr0 = bbase + qt * 64 + w * 16 + (lane >> 2);
        const int gr1 = gr0 + 8;
#pragma unroll
        for (int nt = 0; nt < 16; nt++) {
            int col = nt * 8 + 2 * (lane & 3);
            *(float2*)(out + (size_t)gr0 * HDIM + col) =
                make_float2(o[nt][0] * inv0, o[nt][1] * inv0);
            *(float2*)(out + (size_t)gr1 * HDIM + col) =
                make_float2(o[nt][2] * inv1, o[nt][3] * inv1);
        }
    }
}

// ---------------------------------------------------------------------------
extern "C" void kernel_launch(void* const* d_in, const int* in_sizes, int n_in,
                              void* d_out, int out_size)
{
    const float* x  = (const float*)d_in[0];
    const float* Wk = (const float*)d_in[1];
    const float* Wq = (const float*)d_in[2];
    const float* Wv = (const float*)d_in[3];
    float* out = (float*)d_out;

    static bool attr_set = false;
    if (!attr_set) {
        cudaFuncSetAttribute(proj_mma_kernel,
                             cudaFuncAttributeMaxDynamicSharedMemorySize, PR_SMEM);
        cudaFuncSetAttribute(attn_mma_kernel,
                             cudaFuncAttributeMaxDynamicSharedMemorySize, AT_SMEM);
        attr_set = true;
    }

    // 1) split weights to bf16 hi/lo
    wsplit_kernel<<<(3 * HDIM * EMB + 255) / 256, 256>>>(Wk, Wq, Wv);

    // 2) Q/K/V projections on tensor cores (bf16-split) — R3 proj, 3 CTAs/SM
    proj_mma_kernel<<<dim3(128, 3), 256, PR_SMEM>>>(x);

    // 3) causal flash attention on tensor cores (bf16-split), Q in registers
    attn_mma_kernel<<<dim3(32, BATCH), 128, AT_SMEM>>>(out);
}

// round 9
// speedup vs baseline: 1.0948x; 1.0190x over previous
#include <cuda_runtime.h>
#include <cuda_bf16.h>
#include <math.h>
#include <cstdint>

#define BATCH 4
#define SEQ   4096
#define EMB   1024
#define HDIM  128

// ---------------------------------------------------------------------------
// scratch (allocation-free: __device__ globals) — all bf16 hi/lo split pairs
// ---------------------------------------------------------------------------
__device__ __nv_bfloat16 g_Qhi[(size_t)BATCH * SEQ * HDIM];
__device__ __nv_bfloat16 g_Qlo[(size_t)BATCH * SEQ * HDIM];
__device__ __nv_bfloat16 g_Khi[(size_t)BATCH * SEQ * HDIM];
__device__ __nv_bfloat16 g_Klo[(size_t)BATCH * SEQ * HDIM];
__device__ __nv_bfloat16 g_Vhi[(size_t)BATCH * SEQ * HDIM];
__device__ __nv_bfloat16 g_Vlo[(size_t)BATCH * SEQ * HDIM];
// split weights: [which][HDIM][EMB], which: 0=K,1=Q,2=V
__device__ __nv_bfloat16 g_Whi[3 * HDIM * EMB];
__device__ __nv_bfloat16 g_Wlo[3 * HDIM * EMB];

// ===========================================================================
// mma.sync / ldmatrix / cp.async helpers (baseline PTX, no 'a' features)
// ===========================================================================
__device__ __forceinline__ uint32_t smem_to_u32(const void* p) {
    uint32_t a;
    asm("{ .reg .u64 t; cvta.to.shared.u64 t, %1; cvt.u32.u64 %0, t; }"
        : "=r"(a) : "l"(p));
    return a;
}

__device__ __forceinline__ void ldsm_x4(uint32_t addr,
    uint32_t& r0, uint32_t& r1, uint32_t& r2, uint32_t& r3) {
    asm volatile("ldmatrix.sync.aligned.m8n8.x4.shared.b16 {%0,%1,%2,%3}, [%4];"
        : "=r"(r0), "=r"(r1), "=r"(r2), "=r"(r3) : "r"(addr));
}

__device__ __forceinline__ void ldsm_x4_t(uint32_t addr,
    uint32_t& r0, uint32_t& r1, uint32_t& r2, uint32_t& r3) {
    asm volatile("ldmatrix.sync.aligned.m8n8.x4.trans.shared.b16 {%0,%1,%2,%3}, [%4];"
        : "=r"(r0), "=r"(r1), "=r"(r2), "=r"(r3) : "r"(addr));
}

__device__ __forceinline__ void mma_bf16(float& c0, float& c1, float& c2, float& c3,
    uint32_t a0, uint32_t a1, uint32_t a2, uint32_t a3, uint32_t b0, uint32_t b1) {
    asm volatile(
        "mma.sync.aligned.m16n8k16.row.col.f32.bf16.bf16.f32 "
        "{%0,%1,%2,%3}, {%4,%5,%6,%7}, {%8,%9}, {%0,%1,%2,%3};"
        : "+f"(c0), "+f"(c1), "+f"(c2), "+f"(c3)
        : "r"(a0), "r"(a1), "r"(a2), "r"(a3), "r"(b0), "r"(b1));
}

#define CP_ASYNC16(dst, src) \
    asm volatile("cp.async.cg.shared.global [%0], [%1], 16;" :: "r"(dst), "l"(src))
#define CP_COMMIT()  asm volatile("cp.async.commit_group;" ::: "memory")
#define CP_WAIT0()   asm volatile("cp.async.wait_group 0;" ::: "memory")

// base-2 exp via MUFU (handles -inf -> 0, big-negative -> 0)
__device__ __forceinline__ float ex2(float x) {
    float y;
    asm("ex2.approx.f32 %0, %1;" : "=f"(y) : "f"(x));
    return y;
}

// pack two floats into bf16x2 hi + residual lo
__device__ __forceinline__ void split2(float x0, float x1, uint32_t& hi, uint32_t& lo) {
    __nv_bfloat16 h0 = __float2bfloat16(x0);
    __nv_bfloat16 h1 = __float2bfloat16(x1);
    __nv_bfloat16 g0 = __float2bfloat16(x0 - __bfloat162float(h0));
    __nv_bfloat16 g1 = __float2bfloat16(x1 - __bfloat162float(h1));
    hi = (uint32_t)__bfloat16_as_ushort(h0) | ((uint32_t)__bfloat16_as_ushort(h1) << 16);
    lo = (uint32_t)__bfloat16_as_ushort(g0) | ((uint32_t)__bfloat16_as_ushort(g1) << 16);
}

// ===========================================================================
// Weight split prepass: W (fp32) -> (hi, lo) bf16
// ===========================================================================
__global__ __launch_bounds__(256) void wsplit_kernel(
    const float* __restrict__ Wk,
    const float* __restrict__ Wq,
    const float* __restrict__ Wv)
{
    int idx = blockIdx.x * 256 + threadIdx.x;
    if (idx >= 3 * HDIM * EMB) return;
    int which = idx >> 17;
    int within = idx & ((HDIM * EMB) - 1);
    const float* W = (which == 0) ? Wk : (which == 1) ? Wq : Wv;
    float w = W[within];
    __nv_bfloat16 hi = __float2bfloat16(w);
    __nv_bfloat16 lo = __float2bfloat16(w - __bfloat162float(hi));
    g_Whi[idx] = hi;
    g_Wlo[idx] = lo;
}

// ===========================================================================
// Projection GEMM via mma.sync bf16-split — R3 version (73728 B smem,
// 3 CTAs/SM; synchronous loads hidden by cross-CTA TLP).
// grid (128 m-tiles, 3 heads), 256 threads (8 warps x 16 rows = 128 rows).
// ===========================================================================
#define PR_ROWB 144               // 64 bf16 = 128B + 16B pad
#define PR_AHI  0
#define PR_ALO  18432             // 128*144
#define PR_BHI  36864
#define PR_BLO  55296
#define PR_SMEM 73728

extern __shared__ char dsmem[];

__global__ __launch_bounds__(256) void proj_mma_kernel(const float* __restrict__ x)
{
    char* smem = dsmem;
    uint32_t sb = smem_to_u32(smem);
    const int tid  = threadIdx.x;
    const int lane = tid & 31;
    const int w    = tid >> 5;
    const int m0   = blockIdx.x * 128;
    const int which = blockIdx.y;

    // ldmatrix lane offsets
    const uint32_t a_off = (uint32_t)(w * 16 + (lane & 15)) * PR_ROWB
                         + (uint32_t)((lane >> 4) << 3) * 2;
    const uint32_t b_off = (uint32_t)((lane & 7) + ((lane >> 4) << 3)) * PR_ROWB
                         + (uint32_t)(((lane >> 3) & 1) << 3) * 2;

    float o[16][4];
#pragma unroll
    for (int t = 0; t < 16; t++)
#pragma unroll
        for (int k = 0; k < 4; k++) o[t][k] = 0.0f;

    const int a_row  = tid >> 1;
    const int a_half = tid & 1;

    for (int e0 = 0; e0 < EMB; e0 += 64) {
        __syncthreads();
        // ---- A: load x fp32, split to bf16 hi/lo ----
        {
            const float* xr = x + (size_t)(m0 + a_row) * EMB + e0 + a_half * 32;
            uint32_t abase = (uint32_t)a_row * PR_ROWB + (uint32_t)(a_half * 32) * 2;
#pragma unroll
            for (int i = 0; i < 8; i++) {
                float4 v = *(const float4*)(xr + i * 4);
                uint32_t h01, l01, h23, l23;
                split2(v.x, v.y, h01, l01);
                split2(v.z, v.w, h23, l23);
                uint32_t off = abase + (uint32_t)(i * 4) * 2;
                *(uint32_t*)(smem + PR_AHI + off)     = h01;
                *(uint32_t*)(smem + PR_AHI + off + 4) = h23;
                *(uint32_t*)(smem + PR_ALO + off)     = l01;
                *(uint32_t*)(smem + PR_ALO + off + 4) = l23;
            }
        }
        // ---- B: copy pre-split W tiles ----
#pragma unroll
        for (int j = 0; j < 4; j++) {
            int idx = tid + j * 256;          // 0..1023
            int row = idx >> 3, c8 = idx & 7;
            size_t gsrc = (size_t)(which * HDIM + row) * EMB + e0 + c8 * 8;
            uint32_t doff = (uint32_t)row * PR_ROWB + (uint32_t)c8 * 16;
            *(uint4*)(smem + PR_BHI + doff) = *(const uint4*)(g_Whi + gsrc);
            *(uint4*)(smem + PR_BLO + doff) = *(const uint4*)(g_Wlo + gsrc);
        }
        __syncthreads();

        // ---- MMA ----
#pragma unroll
        for (int kk = 0; kk < 4; kk++) {
            uint32_t ah0, ah1, ah2, ah3, al0, al1, al2, al3;
            ldsm_x4(sb + PR_AHI + a_off + kk * 32, ah0, ah1, ah2, ah3);
            ldsm_x4(sb + PR_ALO + a_off + kk * 32, al0, al1, al2, al3);
#pragma unroll
            for (int np = 0; np < 8; np++) {
                uint32_t bh0, bh1, bh2, bh3, bl0, bl1, bl2, bl3;
                uint32_t boff = b_off + (uint32_t)(np * 16) * PR_ROWB + kk * 32;
                ldsm_x4(sb + PR_BHI + boff, bh0, bh1, bh2, bh3);
                ldsm_x4(sb + PR_BLO + boff, bl0, bl1, bl2, bl3);
                int t0 = 2 * np, t1 = t0 + 1;
                mma_bf16(o[t0][0], o[t0][1], o[t0][2], o[t0][3], ah0, ah1, ah2, ah3, bh0, bh1);
                mma_bf16(o[t0][0], o[t0][1], o[t0][2], o[t0][3], ah0, ah1, ah2, ah3, bl0, bl1);
                mma_bf16(o[t0][0], o[t0][1], o[t0][2], o[t0][3], al0, al1, al2, al3, bh0, bh1);
                mma_bf16(o[t1][0], o[t1][1], o[t1][2], o[t1][3], ah0, ah1, ah2, ah3, bh2, bh3);
                mma_bf16(o[t1][0], o[t1][1], o[t1][2], o[t1][3], ah0, ah1, ah2, ah3, bl2, bl3);
                mma_bf16(o[t1][0], o[t1][1], o[t1][2], o[t1][3], al0, al1, al2, al3, bh2, bh3);
            }
        }
    }

    // ---- epilogue: split result, write bf16 hi/lo ----
    // Q pre-scaled by (1/32)*log2(e) so attention softmax runs in base-2.
    const float scale = (which == 1) ? (0.03125f * 1.44269504f) : 1.0f;
    __nv_bfloat16* dh = (which == 0) ? g_Khi : (which == 1) ? g_Qhi : g_Vhi;
    __nv_bfloat16* dl = (which == 0) ? g_Klo : (which == 1) ? g_Qlo : g_Vlo;
    const int r0 = m0 + w * 16 + (lane >> 2);
    const int r1 = r0 + 8;
#pragma unroll
    for (int nt = 0; nt < 16; nt++) {
        int col = nt * 8 + 2 * (lane & 3);
        uint32_t hi, lo;
        split2(o[nt][0] * scale, o[nt][1] * scale, hi, lo);
        *(uint32_t*)(dh + (size_t)r0 * HDIM + col) = hi;
        *(uint32_t*)(dl + (size_t)r0 * HDIM + col) = lo;
        split2(o[nt][2] * scale, o[nt][3] * scale, hi, lo);
        *(uint32_t*)(dh + (size_t)r1 * HDIM + col) = hi;
        *(uint32_t*)(dl + (size_t)r1 * HDIM + col) = lo;
    }
}

// ===========================================================================
// Flash attention via mma.sync bf16-split, 8 warps (2/SMSP), FA2 key-split:
// warps 0-3 own keys [0:32) of every k-tile, warps 4-7 own keys [32:64).
// Each half keeps INDEPENDENT (m, l, O) across the whole key loop — zero
// per-iteration cross-warp sync; one merge per q-tile at the end.
// grid (32 pairs, 4 batch), 256 threads. BQ=64, BK=64, pair balancing.
// ===========================================================================
#define AT_ROWB 272               // 128 bf16 = 256B + 16B pad
#define AT_TILE 17408             // 64*272
#define AT_QHI  0
#define AT_QLO  17408
#define AT_KV   34816             // + buf*69632 : KHI,KLO,VHI,VLO
#define AT_BUF  69632
#define AT_SMEM 174080
#define M_INIT  (-1e30f)

__device__ __forceinline__ void prefetch_kv(uint32_t sb_buf, int grow, int tid)
{
#pragma unroll
    for (int t = 0; t < 4; t++) {
        const __nv_bfloat16* g =
            (t == 0) ? g_Khi : (t == 1) ? g_Klo : (t == 2) ? g_Vhi : g_Vlo;
        g += (size_t)grow * HDIM;
        uint32_t tb = sb_buf + t * AT_TILE;
#pragma unroll
        for (int j = 0; j < 4; j++) {
            int idx = tid + j * 256;
            int row = idx >> 4, c16 = idx & 15;
            uint32_t dst = tb + (uint32_t)row * AT_ROWB + (uint32_t)c16 * 16;
            CP_ASYNC16(dst, (const void*)(g + (size_t)row * HDIM + c16 * 8));
        }
    }
    CP_COMMIT();
}

__global__ __launch_bounds__(256) void attn_mma_kernel(float* __restrict__ out)
{
    char* smem = dsmem;
    uint32_t sb = smem_to_u32(smem);
    const int tid  = threadIdx.x;
    const int lane = tid & 31;
    const int w    = tid >> 5;
    const int wq   = w & 3;           // query-row group (16 rows)
    const int nh   = w >> 2;          // key half: 0 -> [0:32), 1 -> [32:64)
    const int b    = blockIdx.y;
    const int pair = blockIdx.x;
    const int bbase = b * SEQ;

    // ldmatrix lane offsets
    const uint32_t a_off = (uint32_t)(wq * 16 + (lane & 15)) * AT_ROWB
                         + (uint32_t)((lane >> 4) << 3) * 2;
    const uint32_t b_off = (uint32_t)(nh * 32 + (lane & 7) + ((lane >> 4) << 3)) * AT_ROWB
                         + (uint32_t)(((lane >> 3) & 1) << 3) * 2;
    const uint32_t v_off = (uint32_t)(nh * 32 + (lane & 7) + (((lane >> 3) & 1) << 3)) * AT_ROWB
                         + (uint32_t)((lane >> 4) << 3) * 2;
    const int r0 = wq * 16 + (lane >> 2);   // tile-local row (0..63)

    for (int half = 0; half < 2; half++) {
        const int qt = half ? (63 - pair) : pair;
        const int nkt = qt + 1;

        // ---- stage Q tile (hi/lo) into smem ----
        __syncthreads();
        {
            const size_t gq = (size_t)(bbase + qt * 64) * HDIM;
#pragma unroll
            for (int j = 0; j < 4; j++) {
                int idx = tid + j * 256;
                int row = idx >> 4, c16 = idx & 15;
                uint32_t doff = (uint32_t)row * AT_ROWB + (uint32_t)c16 * 16;
                *(uint4*)(smem + AT_QHI + doff) =
                    *(const uint4*)(g_Qhi + gq + (size_t)row * HDIM + c16 * 8);
                *(uint4*)(smem + AT_QLO + doff) =
                    *(const uint4*)(g_Qlo + gq + (size_t)row * HDIM + c16 * 8);
            }
        }
        __syncthreads();

        float o[16][4];
#pragma unroll
        for (int t = 0; t < 16; t++)
#pragma unroll
            for (int k = 0; k < 4; k++) o[t][k] = 0.0f;
        float m0 = M_INIT, m1 = M_INIT, l0 = 0.0f, l1 = 0.0f;

        prefetch_kv(sb + AT_KV, bbase, tid);   // kt = 0 into buf 0

        for (int kt = 0; kt < nkt; kt++) {
            CP_WAIT0();
            __syncthreads();
            if (kt + 1 < nkt)
                prefetch_kv(sb + AT_KV + ((kt + 1) & 1) * AT_BUF,
                            bbase + (kt + 1) * 64, tid);
            const uint32_t kb = sb + AT_KV + (kt & 1) * AT_BUF;

            // ---- S = Q K^T on this warp's 32-key half (3-product split) ----
            float s[4][4];
#pragma unroll
            for (int t = 0; t < 4; t++)
#pragma unroll
                for (int k = 0; k < 4; k++) s[t][k] = 0.0f;

#pragma unroll
            for (int kk = 0; kk < 8; kk++) {
                uint32_t qh0, qh1, qh2, qh3, ql0, ql1, ql2, ql3;
                ldsm_x4(sb + AT_QHI + a_off + kk * 32, qh0, qh1, qh2, qh3);
                ldsm_x4(sb + AT_QLO + a_off + kk * 32, ql0, ql1, ql2, ql3);
#pragma unroll
                for (int np = 0; np < 2; np++) {
                    uint32_t kh0, kh1, kh2, kh3, kl0, kl1, kl2, kl3;
                    uint32_t boff = b_off + (uint32_t)(np * 16) * AT_ROWB + kk * 32;
                    ldsm_x4(kb + 0 * AT_TILE + boff, kh0, kh1, kh2, kh3);
                    ldsm_x4(kb + 1 * AT_TILE + boff, kl0, kl1, kl2, kl3);
                    int t0 = 2 * np, t1 = t0 + 1;
                    mma_bf16(s[t0][0], s[t0][1], s[t0][2], s[t0][3], qh0, qh1, qh2, qh3, kh0, kh1);
                    mma_bf16(s[t1][0], s[t1][1], s[t1][2], s[t1][3], qh0, qh1, qh2, qh3, kh2, kh3);
                    mma_bf16(s[t0][0], s[t0][1], s[t0][2], s[t0][3], qh0, qh1, qh2, qh3, kl0, kl1);
                    mma_bf16(s[t1][0], s[t1][1], s[t1][2], s[t1][3], qh0, qh1, qh2, qh3, kl2, kl3);
                    mma_bf16(s[t0][0], s[t0][1], s[t0][2], s[t0][3], ql0, ql1, ql2, ql3, kh0, kh1);
                    mma_bf16(s[t1][0], s[t1][1], s[t1][2], s[t1][3], ql0, ql1, ql2, ql3, kh2, kh3);
                }
            }

            // ---- causal mask on diagonal tile ----
            if (kt == qt) {
                const int rr0 = r0;
                const int rr1 = r0 + 8;
#pragma unroll
                for (int nt = 0; nt < 4; nt++) {
                    int c = nh * 32 + nt * 8 + 2 * (lane & 3);
                    if (c     > rr0) s[nt][0] = -INFINITY;
                    if (c + 1 > rr0) s[nt][1] = -INFINITY;
                    if (c     > rr1) s[nt][2] = -INFINITY;
                    if (c + 1 > rr1) s[nt][3] = -INFINITY;
                }
            }

            // ---- online softmax (base-2, fully independent per key-half) ----
            float rmax0 = -INFINITY, rmax1 = -INFINITY;
#pragma unroll
            for (int nt = 0; nt < 4; nt++) {
                rmax0 = fmaxf(rmax0, fmaxf(s[nt][0], s[nt][1]));
                rmax1 = fmaxf(rmax1, fmaxf(s[nt][2], s[nt][3]));
            }
            rmax0 = fmaxf(rmax0, __shfl_xor_sync(0xffffffffu, rmax0, 1));
            rmax0 = fmaxf(rmax0, __shfl_xor_sync(0xffffffffu, rmax0, 2));
            rmax1 = fmaxf(rmax1, __shfl_xor_sync(0xffffffffu, rmax1, 1));
            rmax1 = fmaxf(rmax1, __shfl_xor_sync(0xffffffffu, rmax1, 2));

            float mn0 = fmaxf(m0, rmax0), mn1 = fmaxf(m1, rmax1);
            float alpha0 = ex2(m0 - mn0), alpha1 = ex2(m1 - mn1);
            m0 = mn0; m1 = mn1;

            float sum0 = 0.0f, sum1 = 0.0f;
#pragma unroll
            for (int nt = 0; nt < 4; nt++) {
                s[nt][0] = ex2(s[nt][0] - mn0);
                s[nt][1] = ex2(s[nt][1] - mn0);
                s[nt][2] = ex2(s[nt][2] - mn1);
                s[nt][3] = ex2(s[nt][3] - mn1);
                sum0 += s[nt][0] + s[nt][1];
                sum1 += s[nt][2] + s[nt][3];
            }
            sum0 += __shfl_xor_sync(0xffffffffu, sum0, 1);
            sum0 += __shfl_xor_sync(0xffffffffu, sum0, 2);
            sum1 += __shfl_xor_sync(0xffffffffu, sum1, 1);
            sum1 += __shfl_xor_sync(0xffffffffu, sum1, 2);
            l0 = l0 * alpha0 + sum0;
            l1 = l1 * alpha1 + sum1;

#pragma unroll
            for (int t = 0; t < 16; t++) {
                o[t][0] *= alpha0; o[t][1] *= alpha0;
                o[t][2] *= alpha1; o[t][3] *= alpha1;
            }

            // ---- O += P V over this warp's 32-key range (split) ----
#pragma unroll
            for (int kk2 = 0; kk2 < 2; kk2++) {
                int t0 = 2 * kk2, t1 = t0 + 1;
                uint32_t ah0, ah1, ah2, ah3, al0, al1, al2, al3;
                split2(s[t0][0], s[t0][1], ah0, al0);
                split2(s[t0][2], s[t0][3], ah1, al1);
                split2(s[t1][0], s[t1][1], ah2, al2);
                split2(s[t1][2], s[t1][3], ah3, al3);
#pragma unroll
                for (int np = 0; np < 8; np++) {
                    uint32_t vh0, vh1, vh2, vh3, vl0, vl1, vl2, vl3;
                    uint32_t voff = v_off + (uint32_t)(kk2 * 16) * AT_ROWB + np * 32;
                    ldsm_x4_t(kb + 2 * AT_TILE + voff, vh0, vh1, vh2, vh3);
                    ldsm_x4_t(kb + 3 * AT_TILE + voff, vl0, vl1, vl2, vl3);
                    int u0 = 2 * np, u1 = u0 + 1;
                    mma_bf16(o[u0][0], o[u0][1], o[u0][2], o[u0][3], ah0, ah1, ah2, ah3, vh0, vh1);
                    mma_bf16(o[u1][0], o[u1][1], o[u1][2], o[u1][3], ah0, ah1, ah2, ah3, vh2, vh3);
                    mma_bf16(o[u0][0], o[u0][1], o[u0][2], o[u0][3], ah0, ah1, ah2, ah3, vl0, vl1);
                    mma_bf16(o[u1][0], o[u1][1], o[u1][2], o[u1][3], ah0, ah1, ah2, ah3, vl2, vl3);
                    mma_bf16(o[u0][0], o[u0][1], o[u0][2], o[u0][3], al0, al1, al2, al3, vh0, vh1);
                    mma_bf16(o[u1][0], o[u1][1], o[u1][2], o[u1][3], al0, al1, al2, al3, vh2, vh3);
                }
            }
        }

        // ---- merge the two key-halves' (O, m, l), normalize, store ----
        __syncthreads();   // all PV reads of KV smem done; reuse as scratch
        float* O1 = (float*)(smem + AT_KV);             // [64][128]
        float* M1 = (float*)(smem + AT_KV + 32768);     // [64]
        float* L1 = M1 + 64;                            // [64]
        if (nh == 1) {
#pragma unroll
            for (int nt = 0; nt < 16; nt++) {
                int col = nt * 8 + 2 * (lane & 3);
                *(float2*)(O1 + (r0)     * 128 + col) = make_float2(o[nt][0], o[nt][1]);
                *(float2*)(O1 + (r0 + 8) * 128 + col) = make_float2(o[nt][2], o[nt][3]);
            }
            if ((lane & 3) == 0) {
                M1[r0] = m0;  M1[r0 + 8] = m1;
                L1[r0] = l0;  L1[r0 + 8] = l1;
            }
        }
        __syncthreads();
        if (nh == 0) {
            float m1a = M1[r0],     l1a = L1[r0];
            float m1b = M1[r0 + 8], l1b = L1[r0 + 8];
            float Ma = fmaxf(m0, m1a), Mb = fmaxf(m1, m1b);
            float b0a = ex2(m0 - Ma),  b1a = ex2(m1a - Ma);
            float b0b = ex2(m1 - Mb),  b1b = ex2(m1b - Mb);
            float invLa = 1.0f / (l0 * b0a + l1a * b1a);
            float invLb = 1.0f / (l1 * b0b + l1b * b1b);
            const int gr0 = bbase + qt * 64 + r0;
            const int gr1 = gr0 + 8;
#pragma unroll
            for (int nt = 0; nt < 16; nt++) {
                int col = nt * 8 + 2 * (lane & 3);
                float2 p0 = *(const float2*)(O1 + (r0)     * 128 + col);
                float2 p1 = *(const float2*)(O1 + (r0 + 8) * 128 + col);
                *(float2*)(out + (size_t)gr0 * HDIM + col) = make_float2(
                    (o[nt][0] * b0a + p0.x * b1a) * invLa,
                    (o[nt][1] * b0a + p0.y * b1a) * invLa);
                *(float2*)(out + (size_t)gr1 * HDIM + col) = make_float2(
                    (o[nt][2] * b0b + p1.x * b1b) * invLb,
                    (o[nt][3] * b0b + p1.y * b1b) * invLb);
            }
        }
    }
}

// ---------------------------------------------------------------------------
extern "C" void kernel_launch(void* const* d_in, const int* in_sizes, int n_in,
                              void* d_out, int out_size)
{
    const float* x  = (const float*)d_in[0];
    const float* Wk = (const float*)d_in[1];
    const float* Wq = (const float*)d_in[2];
    const float* Wv = (const float*)d_in[3];
    float* out = (float*)d_out;

    static bool attr_set = false;
    if (!attr_set) {
        cudaFuncSetAttribute(proj_mma_kernel,
                             cudaFuncAttributeMaxDynamicSharedMemorySize, PR_SMEM);
        cudaFuncSetAttribute(attn_mma_kernel,
                             cudaFuncAttributeMaxDynamicSharedMemorySize, AT_SMEM);
        attr_set = true;
    }

    // 1) split weights to bf16 hi/lo
    wsplit_kernel<<<(3 * HDIM * EMB + 255) / 256, 256>>>(Wk, Wq, Wv);

    // 2) Q/K/V projections on tensor cores (bf16-split) — R3 proj, 3 CTAs/SM
    proj_mma_kernel<<<dim3(128, 3), 256, PR_SMEM>>>(x);

    // 3) causal flash attention, 8 warps, sync-free FA2 key-split halves
    attn_mma_kernel<<<dim3(32, BATCH), 256, AT_SMEM>>>(out);
}